// round 2
// baseline (speedup 1.0000x reference)
#include <cuda_runtime.h>
#include <cstdint>

typedef unsigned char u8;
typedef unsigned int u32;

#define BATCH 4096

// ---------------- static device scratch (no allocations allowed) ----------------
// Per-layer LUT-matrices: M[k][a][o] = lut[a + aoff][qw[o*K + k]]
__device__ __align__(128) float g_M1[25 * 256 * 8];     // conv1: K=25, full a-range, O=6 padded to 8
__device__ __align__(128) float g_M2[150 * 128 * 16];   // conv2: K=150, a in [128,255], O=16
__device__ __align__(128) float g_M3[256 * 128 * 120];  // fc1
__device__ __align__(128) float g_M4[120 * 128 * 84];   // fc2
__device__ __align__(128) float g_M5[84 * 128 * 10];    // fc3

__device__ u8    g_qx [BATCH * 784];
__device__ float g_h1 [BATCH * 6 * 144];
__device__ u8    g_qh1[BATCH * 6 * 144];
__device__ float g_h2 [BATCH * 256];
__device__ u8    g_qh2[BATCH * 256];
__device__ float g_h3 [BATCH * 120];
__device__ u8    g_qh3[BATCH * 120];
__device__ float g_h4 [BATCH * 84];
__device__ u8    g_qh4[BATCH * 84];

__device__ u8 g_qw1[150], g_qw2[2400], g_qw3[30720], g_qw4[10080], g_qw5[840];
__device__ float g_sw[5];   // weight scales
__device__ u32 g_amax[5];   // activation max-abs (float bits), per layer input

// ---------------- helpers ----------------
__device__ __forceinline__ float act_scale(int i) {
    float m = __uint_as_float(g_amax[i]);
    return __fdiv_rn(m, 127.0f) + 1e-8f;
}

__device__ __forceinline__ float blockReduceMax(float v, float* sred) {
    #pragma unroll
    for (int off = 16; off; off >>= 1)
        v = fmaxf(v, __shfl_xor_sync(0xFFFFFFFFu, v, off));
    int w = threadIdx.x >> 5;
    int nw = (blockDim.x + 31) >> 5;
    if ((threadIdx.x & 31) == 0) sred[w] = v;
    __syncthreads();
    if (threadIdx.x < 32) {
        v = (threadIdx.x < nw) ? sred[threadIdx.x] : 0.0f;
        #pragma unroll
        for (int off = 16; off; off >>= 1)
            v = fmaxf(v, __shfl_xor_sync(0xFFFFFFFFu, v, off));
    }
    return v;  // valid in thread 0
}

__device__ __forceinline__ u8 quant1(float v, float s) {
    float q = rintf(__fdiv_rn(v, s));
    q = fminf(fmaxf(q, -128.0f), 127.0f);
    return (u8)((int)q + 128);
}

// ---------------- setup kernels ----------------
__global__ void k_zero() {
    if (threadIdx.x < 5) g_amax[threadIdx.x] = 0u;
}

__global__ void k_quant_w(const float* w0, const float* w1, const float* w2,
                          const float* w3, const float* w4) {
    __shared__ float sred[32];
    __shared__ float ss;
    int l = blockIdx.x;
    const float* w; int n; u8* dst;
    if      (l == 0) { w = w0; n = 150;   dst = g_qw1; }
    else if (l == 1) { w = w1; n = 2400;  dst = g_qw2; }
    else if (l == 2) { w = w2; n = 30720; dst = g_qw3; }
    else if (l == 3) { w = w3; n = 10080; dst = g_qw4; }
    else             { w = w4; n = 840;   dst = g_qw5; }
    float m = 0.0f;
    for (int i = threadIdx.x; i < n; i += blockDim.x) m = fmaxf(m, fabsf(w[i]));
    m = blockReduceMax(m, sred);
    if (threadIdx.x == 0) {
        float s = __fdiv_rn(m, 127.0f) + 1e-8f;
        g_sw[l] = s; ss = s;
    }
    __syncthreads();
    float s = ss;
    for (int i = threadIdx.x; i < n; i += blockDim.x) dst[i] = quant1(w[i], s);
}

__global__ void k_buildM(float* dst, const u8* qw, const float* lut,
                         int K, int O, int Opad, int aoff, int nA) {
    int total = K * nA * Opad;
    for (int i = blockIdx.x * blockDim.x + threadIdx.x; i < total;
         i += gridDim.x * blockDim.x) {
        int k = i / (nA * Opad);
        int r = i - k * (nA * Opad);
        int a = r / Opad;
        int o = r - a * Opad;
        dst[i] = (o < O) ? lut[(a + aoff) * 256 + (int)qw[o * K + k]] : 0.0f;
    }
}

__global__ void k_maxabs(const float* src, int n, int idx) {
    __shared__ float sred[32];
    float m = 0.0f;
    for (int i = blockIdx.x * blockDim.x + threadIdx.x; i < n;
         i += gridDim.x * blockDim.x)
        m = fmaxf(m, fabsf(src[i]));
    m = blockReduceMax(m, sred);
    if (threadIdx.x == 0) atomicMax(&g_amax[idx], __float_as_uint(m));
}

__global__ void k_quant_act(const float* src, u8* dst, int n, int idx) {
    float s = act_scale(idx);
    for (int i = blockIdx.x * blockDim.x + threadIdx.x; i < n;
         i += gridDim.x * blockDim.x)
        dst[i] = quant1(src[i], s);
}

// ---------------- conv1: qx -> h1 (relu+pool fused), maxabs -> g_amax[1] ----------------
__global__ void __launch_bounds__(288) k_conv1(const float* b1) {
    __shared__ u8 sImg[1568];      // 2 images
    __shared__ float sred[32];
    int blk = blockIdx.x, tid = threadIdx.x;
    const u32* src = (const u32*)(g_qx + (size_t)blk * 1568);
    for (int i = tid; i < 392; i += 288) ((u32*)sImg)[i] = src[i];
    __syncthreads();

    int img = tid / 144, pos = tid - img * 144;
    int py = pos / 12, px = pos - py * 12;
    float s = act_scale(0) * g_sw[0];
    float bb[6];
    #pragma unroll
    for (int o = 0; o < 6; o++) bb[o] = __ldg(b1 + o);

    float best[6] = {0, 0, 0, 0, 0, 0};   // relu outputs >= 0
    const u8* base = sImg + img * 784;
    for (int dy = 0; dy < 2; dy++) {
        for (int dx = 0; dx < 2; dx++) {
            float a0 = 0, a1 = 0, a2 = 0, a3 = 0, a4 = 0, a5 = 0;
            const u8* ip = base + (py * 2 + dy) * 28 + (px * 2 + dx);
            #pragma unroll
            for (int i = 0; i < 5; i++) {
                #pragma unroll
                for (int j = 0; j < 5; j++) {
                    int a = ip[i * 28 + j];
                    const float4* m = reinterpret_cast<const float4*>(g_M1)
                                    + (((i * 5 + j) * 256 + a) << 1);
                    float4 v0 = __ldg(m);
                    float4 v1 = __ldg(m + 1);
                    a0 += v0.x; a1 += v0.y; a2 += v0.z; a3 += v0.w;
                    a4 += v1.x; a5 += v1.y;
                }
            }
            float acc[6] = {a0, a1, a2, a3, a4, a5};
            #pragma unroll
            for (int o = 0; o < 6; o++) {
                float v = fmaxf(s * acc[o] + bb[o], 0.0f);
                best[o] = fmaxf(best[o], v);
            }
        }
    }
    int b = blk * 2 + img;
    float mymax = 0.0f;
    #pragma unroll
    for (int o = 0; o < 6; o++) {
        g_h1[(size_t)(b * 6 + o) * 144 + pos] = best[o];
        mymax = fmaxf(mymax, best[o]);
    }
    float bm = blockReduceMax(mymax, sred);
    if (tid == 0) atomicMax(&g_amax[1], __float_as_uint(bm));
}

// ---------------- conv2: qh1 -> h2 (relu+pool), maxabs -> g_amax[2] ----------------
__global__ void __launch_bounds__(256) k_conv2(const float* b2) {
    __shared__ u8 sImg[4 * 864];
    __shared__ float sVal[4 * 64 * 16];
    __shared__ float sred[32];
    int blk = blockIdx.x, tid = threadIdx.x;
    const u32* src = (const u32*)(g_qh1 + (size_t)blk * 3456);
    for (int i = tid; i < 864; i += 256) ((u32*)sImg)[i] = src[i];
    __syncthreads();

    int img = tid >> 6, pos = tid & 63;
    int y = pos >> 3, x = pos & 7;
    float acc[16];
    #pragma unroll
    for (int o = 0; o < 16; o++) acc[o] = 0.0f;

    const u8* base = sImg + img * 864 + y * 12 + x;
    for (int c = 0; c < 6; c++) {
        const u8* cp = base + c * 144;
        #pragma unroll
        for (int i = 0; i < 5; i++) {
            #pragma unroll
            for (int j = 0; j < 5; j++) {
                int ai = (int)cp[i * 12 + j] - 128;
                int k = c * 25 + i * 5 + j;
                const float4* m = reinterpret_cast<const float4*>(g_M2)
                                + ((k * 128 + ai) << 2);
                float4 v0 = __ldg(m);
                float4 v1 = __ldg(m + 1);
                float4 v2 = __ldg(m + 2);
                float4 v3 = __ldg(m + 3);
                acc[0] += v0.x;  acc[1] += v0.y;  acc[2] += v0.z;  acc[3] += v0.w;
                acc[4] += v1.x;  acc[5] += v1.y;  acc[6] += v1.z;  acc[7] += v1.w;
                acc[8] += v2.x;  acc[9] += v2.y;  acc[10] += v2.z; acc[11] += v2.w;
                acc[12] += v3.x; acc[13] += v3.y; acc[14] += v3.z; acc[15] += v3.w;
            }
        }
    }
    float s = act_scale(1) * g_sw[1];
    #pragma unroll
    for (int o = 0; o < 16; o++)
        sVal[(img * 64 + pos) * 16 + o] = fmaxf(s * acc[o] + __ldg(b2 + o), 0.0f);
    __syncthreads();

    float mymax = 0.0f;
    #pragma unroll
    for (int t = 0; t < 4; t++) {
        int id = tid + 256 * t;             // 0..1023 = 4 img * 16 pooled * 16 ch
        int im = id >> 8;
        int r = id & 255;
        int pp = r >> 4;
        int o = r & 15;
        int py = pp >> 2, px = pp & 3;
        const float* v = &sVal[(im * 64 + (py * 2) * 8 + px * 2) * 16 + o];
        float mv = fmaxf(fmaxf(v[0], v[16]), fmaxf(v[128], v[144]));
        g_h2[(size_t)(blk * 4 + im) * 256 + o * 16 + py * 4 + px] = mv;
        mymax = fmaxf(mymax, mv);
    }
    float bm = blockReduceMax(mymax, sred);
    if (tid == 0) atomicMax(&g_amax[2], __float_as_uint(bm));
}

// ---------------- fc1: qh2 -> h3, maxabs -> g_amax[3] ----------------
__global__ void __launch_bounds__(128) k_fc1(const float* fcb) {
    __shared__ u32 sq[64];
    __shared__ float sred[32];
    int b = blockIdx.x, tid = threadIdx.x;
    if (tid < 64) sq[tid] = ((const u32*)(g_qh2 + (size_t)b * 256))[tid];
    __syncthreads();
    const u8* q = (const u8*)sq;
    float acc = 0.0f;
    if (tid < 120) {
        #pragma unroll 8
        for (int k = 0; k < 256; k++) {
            int ai = (int)q[k] - 128;
            acc += __ldg(&g_M3[(size_t)(k * 128 + ai) * 120 + tid]);
        }
    }
    float s = act_scale(2) * g_sw[2];
    float val = 0.0f;
    if (tid < 120) {
        val = fmaxf(s * acc + __ldg(fcb + tid), 0.0f);
        g_h3[(size_t)b * 120 + tid] = val;
    }
    float bm = blockReduceMax(val, sred);
    if (tid == 0) atomicMax(&g_amax[3], __float_as_uint(bm));
}

// ---------------- fc2: qh3 -> h4, maxabs -> g_amax[4] ----------------
__global__ void __launch_bounds__(96) k_fc2(const float* fcb) {
    __shared__ u32 sq[30];
    __shared__ float sred[32];
    int b = blockIdx.x, tid = threadIdx.x;
    if (tid < 30) sq[tid] = ((const u32*)(g_qh3 + (size_t)b * 120))[tid];
    __syncthreads();
    const u8* q = (const u8*)sq;
    float acc = 0.0f;
    if (tid < 84) {
        #pragma unroll 8
        for (int k = 0; k < 120; k++) {
            int ai = (int)q[k] - 128;
            acc += __ldg(&g_M4[(size_t)(k * 128 + ai) * 84 + tid]);
        }
    }
    float s = act_scale(3) * g_sw[3];
    float val = 0.0f;
    if (tid < 84) {
        val = fmaxf(s * acc + __ldg(fcb + tid), 0.0f);
        g_h4[(size_t)b * 84 + tid] = val;
    }
    float bm = blockReduceMax(val, sred);
    if (tid == 0) atomicMax(&g_amax[4], __float_as_uint(bm));
}

// ---------------- fc3: qh4 -> out ----------------
__global__ void k_fc3(const float* fcb, float* out) {
    int idx = blockIdx.x * blockDim.x + threadIdx.x;
    if (idx >= BATCH * 10) return;
    int b = idx / 10, o = idx - b * 10;
    const u8* q = g_qh4 + (size_t)b * 84;
    float acc = 0.0f;
    #pragma unroll 4
    for (int k = 0; k < 84; k++) {
        int ai = (int)q[k] - 128;
        acc += __ldg(&g_M5[(k * 128 + ai) * 10 + o]);
    }
    float s = act_scale(4) * g_sw[4];
    out[idx] = s * acc + __ldg(fcb + o);
}

// ---------------- launch ----------------
extern "C" void kernel_launch(void* const* d_in, const int* in_sizes, int n_in,
                              void* d_out, int out_size) {
    const float* x   = (const float*)d_in[0];
    const float* lut = (const float*)d_in[1];
    const float* w1  = (const float*)d_in[2];
    const float* b1  = (const float*)d_in[3];
    const float* w2  = (const float*)d_in[4];
    const float* b2  = (const float*)d_in[5];
    const float* w3  = (const float*)d_in[6];
    const float* b3  = (const float*)d_in[7];
    const float* w4  = (const float*)d_in[8];
    const float* b4  = (const float*)d_in[9];
    const float* w5  = (const float*)d_in[10];
    const float* b5  = (const float*)d_in[11];
    float* out = (float*)d_out;

    float *M1p, *M2p, *M3p, *M4p, *M5p;
    u8 *qw1p, *qw2p, *qw3p, *qw4p, *qw5p;
    u8 *qxp, *qh1p, *qh2p, *qh3p, *qh4p;
    float *h1p, *h2p, *h3p, *h4p;
    cudaGetSymbolAddress((void**)&M1p, g_M1);
    cudaGetSymbolAddress((void**)&M2p, g_M2);
    cudaGetSymbolAddress((void**)&M3p, g_M3);
    cudaGetSymbolAddress((void**)&M4p, g_M4);
    cudaGetSymbolAddress((void**)&M5p, g_M5);
    cudaGetSymbolAddress((void**)&qw1p, g_qw1);
    cudaGetSymbolAddress((void**)&qw2p, g_qw2);
    cudaGetSymbolAddress((void**)&qw3p, g_qw3);
    cudaGetSymbolAddress((void**)&qw4p, g_qw4);
    cudaGetSymbolAddress((void**)&qw5p, g_qw5);
    cudaGetSymbolAddress((void**)&qxp, g_qx);
    cudaGetSymbolAddress((void**)&qh1p, g_qh1);
    cudaGetSymbolAddress((void**)&qh2p, g_qh2);
    cudaGetSymbolAddress((void**)&qh3p, g_qh3);
    cudaGetSymbolAddress((void**)&qh4p, g_qh4);
    cudaGetSymbolAddress((void**)&h1p, g_h1);
    cudaGetSymbolAddress((void**)&h2p, g_h2);
    cudaGetSymbolAddress((void**)&h3p, g_h3);
    cudaGetSymbolAddress((void**)&h4p, g_h4);

    k_zero<<<1, 32>>>();
    k_quant_w<<<5, 256>>>(w1, w2, w3, w4, w5);

    // build per-layer LUT matrices
    k_buildM<<<(25 * 256 * 8 + 255) / 256, 256>>>(M1p, qw1p, lut, 25, 6, 8, 0, 256);
    k_buildM<<<(150 * 128 * 16 + 255) / 256, 256>>>(M2p, qw2p, lut, 150, 16, 16, 128, 128);
    k_buildM<<<(256 * 128 * 120 + 255) / 256, 256>>>(M3p, qw3p, lut, 256, 120, 120, 128, 128);
    k_buildM<<<(120 * 128 * 84 + 255) / 256, 256>>>(M4p, qw4p, lut, 120, 84, 84, 128, 128);
    k_buildM<<<(84 * 128 * 10 + 255) / 256, 256>>>(M5p, qw5p, lut, 84, 10, 10, 128, 128);

    // layer 1
    int nx = BATCH * 784;
    k_maxabs<<<2048, 256>>>(x, nx, 0);
    k_quant_act<<<(nx + 255) / 256, 256>>>(x, qxp, nx, 0);
    k_conv1<<<BATCH / 2, 288>>>(b1);

    // layer 2
    int nh1 = BATCH * 6 * 144;
    k_quant_act<<<(nh1 + 255) / 256, 256>>>(h1p, qh1p, nh1, 1);
    k_conv2<<<BATCH / 4, 256>>>(b2);

    // fc1
    int nh2 = BATCH * 256;
    k_quant_act<<<(nh2 + 255) / 256, 256>>>(h2p, qh2p, nh2, 2);
    k_fc1<<<BATCH, 128>>>(b3);

    // fc2
    int nh3 = BATCH * 120;
    k_quant_act<<<(nh3 + 255) / 256, 256>>>(h3p, qh3p, nh3, 3);
    k_fc2<<<BATCH, 96>>>(b4);

    // fc3
    int nh4 = BATCH * 84;
    k_quant_act<<<(nh4 + 255) / 256, 256>>>(h4p, qh4p, nh4, 4);
    k_fc3<<<(BATCH * 10 + 255) / 256, 256>>>(b5, out);
}